// round 9
// baseline (speedup 1.0000x reference)
#include <cuda_runtime.h>
#include <cstdint>

typedef unsigned long long u64;

#define TDIM  1024
#define TROWS 32768
#define RPB   4          // rows per pipeline stage (2 stages in flight)
#define GRID  592        // 4 CTA-slots of work per SM, 2 resident

// ---------- packed f32x2 primitives (sm_103a FFMA2 path) ----------
__device__ __forceinline__ u64 pk2(float lo, float hi) {
    u64 r; asm("mov.b64 %0, {%1, %2};" : "=l"(r) : "f"(lo), "f"(hi)); return r;
}
__device__ __forceinline__ void upk2(u64 v, float& lo, float& hi) {
    asm("mov.b64 {%0, %1}, %2;" : "=f"(lo), "=f"(hi) : "l"(v));
}
__device__ __forceinline__ u64 f2fma(u64 a, u64 b, u64 c) {
    u64 d; asm("fma.rn.f32x2 %0, %1, %2, %3;" : "=l"(d) : "l"(a), "l"(b), "l"(c)); return d;
}
__device__ __forceinline__ u64 f2add(u64 a, u64 b) {
    u64 d; asm("add.rn.f32x2 %0, %1, %2;" : "=l"(d) : "l"(a), "l"(b)); return d;
}
__device__ __forceinline__ u64 f2sub(u64 a, u64 b) {
    u64 d; asm("sub.rn.f32x2 %0, %1, %2;" : "=l"(d) : "l"(a), "l"(b)); return d;
}
__device__ __forceinline__ u64 f2mul(u64 a, u64 b) {
    u64 d; asm("mul.rn.f32x2 %0, %1, %2;" : "=l"(d) : "l"(a), "l"(b)); return d;
}

__global__ void __launch_bounds__(512, 2)
fkan_kernel(const float* __restrict__ x, const float* __restrict__ cf,
            float* __restrict__ out)
{
    const int d0 = threadIdx.x * 2;   // 512 threads cover DIM=1024, 2 cols each

    // ---- per-thread coefficient packs (2 adjacent columns) ----
    // coeffs layout: [d][7] = {c0, cs1, cc1, cs2, cc2, cs3, cc3}
    u64 kc0, ks1, kc1, ks2, kc2, ks3, kc3;
    {
        const float* a = cf + (size_t)d0 * 7;
        const float* b = a + 7;
        kc0 = pk2(a[0], b[0]);
        ks1 = pk2(a[1], b[1]);
        kc1 = pk2(a[2], b[2]);
        ks2 = pk2(a[3], b[3]);
        kc2 = pk2(a[4], b[4]);
        ks3 = pk2(a[5], b[5]);
        kc3 = pk2(a[6], b[6]);
    }

    // ---- hoisted packed constants (thread-invariant -> uniform path) ----
    const u64 INVPI  = pk2(0.3183098861837907f, 0.3183098861837907f);
    const u64 MAGIC  = pk2( 12582912.0f,  12582912.0f);   // 1.5 * 2^23
    const u64 NPI    = pk2(-3.14159274101257f, -3.14159274101257f);
    const u64 S1     = pk2(-1.66050e-1f, -1.66050e-1f);   // sin deg-5 minimax
    const u64 S2     = pk2( 7.61000e-3f,  7.61000e-3f);
    const u64 C2     = pk2(-4.96700e-1f, -4.96700e-1f);   // cos deg-4 minimax
    const u64 C4     = pk2( 3.70500e-2f,  3.70500e-2f);
    const u64 ONE    = pk2( 1.0f,  1.0f);
    const u64 NEG1   = pk2(-1.0f, -1.0f);

    // Fourier correction for one f32x2 pack (two adjacent d columns, same row)
    auto fourier = [&](u64 xp) -> u64 {
        u64 t  = f2fma(xp, INVPI, MAGIC);    // LSB of each half = n & 1
        u64 n  = f2sub(t, MAGIC);            // round-to-nearest(x/pi)
        u64 xr = f2fma(n, NPI, xp);          // r in [-pi/2, pi/2]
        u64 x2 = f2mul(xr, xr);
        u64 q  = f2fma(S2, x2, S1);          // sin deg-5
        q      = f2mul(q, x2);
        u64 s1 = f2fma(q, xr, xr);
        u64 pc = f2fma(C4, x2, C2);          // cos deg-4
        u64 c1 = f2fma(pc, x2, ONE);
        u64 m = (t & 0x0000000100000001ULL) << 31;   // (-1)^n via ALU XOR
        s1 ^= m;
        c1 ^= m;
        u64 tw = f2add(c1, c1);                              // 2*cos
        u64 s2 = f2mul(tw, s1);                              // sin2
        u64 c2 = f2fma(tw, c1, NEG1);                        // cos2
        u64 s3 = f2fma(tw, s2, s1 ^ 0x8000000080000000ULL);  // sin3
        u64 c3 = f2fma(tw, c2, c1 ^ 0x8000000080000000ULL);  // cos3
        u64 acc = f2add(xp, kc0);
        acc = f2fma(s1, ks1, acc);
        acc = f2fma(c1, kc1, acc);
        acc = f2fma(s2, ks2, acc);
        acc = f2fma(c2, kc2, acc);
        acc = f2fma(s3, ks3, acc);
        acc = f2fma(c3, kc3, acc);
        return acc;
    };

    auto loadb = [&](float2* buf, int off) {
#pragma unroll
        for (int j = 0; j < RPB; ++j)
            buf[j] = __ldcs(reinterpret_cast<const float2*>(x + off + j * TDIM));
    };
    auto procb = [&](const float2* buf, int off) {
#pragma unroll
        for (int j = 0; j < RPB; ++j) {
            u64 a0 = fourier(pk2(buf[j].x, buf[j].y));
            float2 ov;
            upk2(a0, ov.x, ov.y);
            __stcs(reinterpret_cast<float2*>(out + off + j * TDIM), ov);
        }
    };

    // software pipeline: load stage i+1 before processing stage i
    const int nq   = TROWS / RPB;            // 8192 stages
    const int step = GRID * RPB * TDIM;      // 32-bit safe (max off < 2^26)
    int q   = blockIdx.x;
    int off = q * (RPB * TDIM) + d0;

    float2 bufA[RPB], bufB[RPB];
    loadb(bufA, off);
    while (true) {
        int offn = off + step;
        bool more = (q + GRID) < nq;         // uniform across block
        if (more) loadb(bufB, offn);
        procb(bufA, off);
        if (!more) break;
        q += GRID; off = offn;

        offn = off + step;
        more = (q + GRID) < nq;
        if (more) loadb(bufA, offn);
        procb(bufB, off);
        if (!more) break;
        q += GRID; off = offn;
    }
}

extern "C" void kernel_launch(void* const* d_in, const int* in_sizes, int n_in,
                              void* d_out, int out_size) {
    const float* x  = (const float*)d_in[0];   // (32768, 1024) fp32
    const float* cf = (const float*)d_in[1];   // (1024, 7) fp32
    float* out = (float*)d_out;
    fkan_kernel<<<GRID, 512>>>(x, cf, out);
}